// round 12
// baseline (speedup 1.0000x reference)
#include <cuda_runtime.h>
#include <math.h>

#define G_ 256
#define M_ 256
#define N_ 65536
#define E_ 1048576
#define C_ 3
#define K_ 5
#define D_ 128

// Interleaved scratch: .x/.y/.z = per-class values, .w = adjacency count.
__device__ float4 g_u0a[N_];         // u0[c] , a0   (row s[g] of Mdj / Adj)
__device__ float4 g_mka[N_];         // mk[c] , ak   (col t[g])
__device__ float4 g_u1a[N_];         // u1[c] , a1   (one propagation step)
__device__ unsigned g_act[N_ / 32];  // bitmask: a0[idx] != 0 (row-active)
__device__ unsigned g_actk[N_ / 32]; // bitmask: ak[idx] != 0 (col-active)
__device__ float g_ukn[C_][G_];      // Mdj[g,s,t]
__device__ float g_ast[G_];          // Adj[g,s,t]
__device__ float g_scal[7];          // info[0..2], l2[3..5], path[6]

// One-instruction 16B atomic add (sm_90+: red.global.add.v4.f32).
__device__ __forceinline__ void red_add_v4(float4* p, float a, float b, float c, float d) {
    asm volatile("red.global.add.v4.f32 [%0], {%1, %2, %3, %4};"
                 :: "l"(p), "f"(a), "f"(b), "f"(c), "f"(d) : "memory");
}

// ---------------- init: zero scratch + attention embedding ----------------
__global__ void __launch_bounds__(256) k_init(const float* __restrict__ hg,
                                              const float* __restrict__ H,
                                              float* __restrict__ out) {
    int gtid = blockIdx.x * 256 + threadIdx.x;
    int gstr = gridDim.x * 256;
    float4 z4 = make_float4(0.f, 0.f, 0.f, 0.f);
    for (int j = gtid; j < N_; j += gstr) {
        g_u0a[j] = z4; g_mka[j] = z4; g_u1a[j] = z4;
    }
    for (int j = gtid; j < N_ / 32; j += gstr) { g_act[j] = 0u; g_actk[j] = 0u; }
    if (gtid < C_ * G_) (&g_ukn[0][0])[gtid] = 0.f;
    if (gtid < G_) g_ast[gtid] = 0.f;
    if (gtid < 7) g_scal[gtid] = 0.f;

    // Attention: one warp per (c,g) unit; 768 units on blocks 0..95.
    int lane = threadIdx.x & 31;
    int w = (blockIdx.x << 3) + (threadIdx.x >> 5);
    if (w < C_ * G_) {
        int c = w >> 8, g = w & 255;
        const float* Hc = H + c * K_ * D_;
        float h[4];
        #pragma unroll
        for (int j = 0; j < 4; j++) h[j] = hg[g * D_ + lane + 32 * j];
        float sc[K_];
        #pragma unroll
        for (int k = 0; k < K_; k++) {
            float x = 0.f;
            #pragma unroll
            for (int j = 0; j < 4; j++) x += h[j] * Hc[k * D_ + lane + 32 * j];
            #pragma unroll
            for (int o = 16; o > 0; o >>= 1) x += __shfl_xor_sync(0xffffffffu, x, o);
            sc[k] = x;
        }
        float mx = sc[0];
        #pragma unroll
        for (int k = 1; k < K_; k++) mx = fmaxf(mx, sc[k]);
        float ex[K_], se = 0.f;
        #pragma unroll
        for (int k = 0; k < K_; k++) { ex[k] = __expf(sc[k] - mx); se += ex[k]; }
        float inv = 1.f / se;
        #pragma unroll
        for (int j = 0; j < 4; j++) {
            float o = 0.f;
            #pragma unroll
            for (int k = 0; k < K_; k++) o += ex[k] * inv * Hc[k * D_ + lane + 32 * j];
            out[w * D_ + lane + 32 * j] = o;
        }
    }
}

// ---------------- edge pass 1: info/l2 + gated row/col scatters ----------------
__global__ void __launch_bounds__(256) k_edge1(const int4* __restrict__ src4,
                                               const int4* __restrict__ dst4,
                                               const float4* __restrict__ sij4,
                                               const int* __restrict__ s,
                                               const int* __restrict__ t) {
    __shared__ int stp[G_];   // s | (t<<16)
    for (int j = threadIdx.x; j < G_; j += 256) stp[j] = s[j] | (t[j] << 16);
    __syncthreads();

    float acc[6] = {0.f, 0.f, 0.f, 0.f, 0.f, 0.f};
    const int NV = E_ / 4;
    int gstr = gridDim.x * 256;
    for (int i = blockIdx.x * 256 + threadIdx.x; i < NV; i += gstr) {
        int4 sv = src4[i];
        int4 dv = dst4[i];
        float4 v0 = sij4[i];
        float4 v1 = sij4[(E_ / 4) + i];
        float4 v2 = sij4[2 * (E_ / 4) + i];
        int svv[4] = {sv.x, sv.y, sv.z, sv.w};
        int dvv[4] = {dv.x, dv.y, dv.z, dv.w};
        float vv[4][3] = {{v0.x, v1.x, v2.x}, {v0.y, v1.y, v2.y},
                          {v0.z, v1.z, v2.z}, {v0.w, v1.w, v2.w}};
        #pragma unroll
        for (int q = 0; q < 4; q++) {
            int g = svv[q] >> 8, r = svv[q] & 255, c = dvv[q] & 255;
            #pragma unroll
            for (int k = 0; k < 3; k++) {
                float x = vv[q][k];
                acc[k]     += x * __logf(2.f * x + 1e-6f)
                            + (1.f - x) * __logf((1.f - x) * (1.f / 0.500001f) + 1e-6f);
                acc[3 + k] += x * x;
            }
            int stv = stp[g];
            bool hr = (r == (stv & 0xffff));
            bool hc = (c == (stv >> 16));
            if (hr) {
                int idx = dvv[q];  // == (g<<8)|c (dst is same-group by construction)
                red_add_v4(&g_u0a[idx], vv[q][0], vv[q][1], vv[q][2], 1.f);
                atomicOr(&g_act[idx >> 5], 1u << (idx & 31));
                if (hc) {
                    atomicAdd(&g_ukn[0][g], vv[q][0]);
                    atomicAdd(&g_ukn[1][g], vv[q][1]);
                    atomicAdd(&g_ukn[2][g], vv[q][2]);
                    atomicAdd(&g_ast[g], 1.f);
                }
            }
            if (hc) {
                int idx = svv[q];  // == (g<<8)|r
                red_add_v4(&g_mka[idx], vv[q][0], vv[q][1], vv[q][2], 1.f);
                atomicOr(&g_actk[idx >> 5], 1u << (idx & 31));
            }
        }
    }
    __shared__ float red[6][8];
    int lane = threadIdx.x & 31, w = threadIdx.x >> 5;
    #pragma unroll
    for (int k = 0; k < 6; k++) {
        float x = acc[k];
        #pragma unroll
        for (int o = 16; o > 0; o >>= 1) x += __shfl_down_sync(0xffffffffu, x, o);
        if (lane == 0) red[k][w] = x;
    }
    __syncthreads();
    if (threadIdx.x < 6) {
        float x = 0.f;
        #pragma unroll
        for (int j = 0; j < 8; j++) x += red[threadIdx.x][j];
        atomicAdd(&g_scal[threadIdx.x], x);
    }
}

// ---------------- edge pass 2: dual-bitmask-gated propagation ----------------
// u1/a1 are only read by k_path at mk-active (actk) cells, so an edge matters
// only if act[src] && actk[dst]: ~0.4% of edges do any work.
__global__ void __launch_bounds__(256) k_edge2(const int4* __restrict__ src4,
                                               const int4* __restrict__ dst4,
                                               const float* __restrict__ sij) {
    __shared__ unsigned act_s[N_ / 32];    // 8 KB: row-active
    __shared__ unsigned actk_s[N_ / 32];   // 8 KB: col-active
    for (int j = threadIdx.x; j < N_ / 32; j += 256) {
        act_s[j] = g_act[j];
        actk_s[j] = g_actk[j];
    }
    __syncthreads();

    const int NV = E_ / 4;
    int gstr = gridDim.x * 256;
    for (int i = blockIdx.x * 256 + threadIdx.x; i < NV; i += gstr) {
        int4 sv = src4[i];
        int4 dv = dst4[i];
        int svv[4] = {sv.x, sv.y, sv.z, sv.w};
        int dvv[4] = {dv.x, dv.y, dv.z, dv.w};
        unsigned b[4];
        #pragma unroll
        for (int q = 0; q < 4; q++)
            b[q] = ((act_s[svv[q] >> 5] >> (svv[q] & 31))
                  & (actk_s[dvv[q] >> 5] >> (dvv[q] & 31))) & 1u;
        int ebase = 4 * i;
        #pragma unroll
        for (int q = 0; q < 4; q++) {
            if (b[q]) {
                float4 u = g_u0a[svv[q]];      // one 16B gather: u0[3], a0
                int e = ebase + q;
                red_add_v4(&g_u1a[dvv[q]],
                           u.x * sij[e], u.y * sij[E_ + e], u.z * sij[2 * E_ + e], u.w);
            }
        }
    }
}

// ---------------- path loss: sparse per-group max over mk-active cells ----------------
// loc values vanish wherever mk==0 (numerator 0, denom clamped), so only cells in
// g_actk (~16/group) matter. One warp per group; lane owns 8 cells via one bitmask
// byte; per-group tail (-log(uk)) computed by lane 0 and atomically summed.
__global__ void __launch_bounds__(256) k_path(const float* __restrict__ pw) {
    int g = (blockIdx.x << 3) + (threadIdx.x >> 5);   // 32 blocks * 8 warps = 256 groups
    int lane = threadIdx.x & 31;
    // bitmask byte for cells m = lane*8 .. lane*8+7
    unsigned wd = g_actk[(g << 3) + (lane >> 2)];
    unsigned byte = (wd >> ((lane & 3) << 3)) & 0xffu;
    float mx[6] = {0.f, 0.f, 0.f, 0.f, 0.f, 0.f};
    while (byte) {
        int j = __ffs(byte) - 1;
        byte &= byte - 1;
        int idx = (g << 8) + (lane << 3) + j;
        float4 u0 = g_u0a[idx];
        float4 mk = g_mka[idx];
        float4 u1 = g_u1a[idx];
        float d0 = u0.w * mk.w; d0 = (d0 == 0.f) ? 1e-8f : d0;
        float d1 = u1.w * mk.w; d1 = (d1 == 0.f) ? 1e-8f : d1;
        float r0 = 1.f / d0, r1 = 1.f / d1;
        mx[0] = fmaxf(mx[0], u0.x * mk.x * r0);
        mx[1] = fmaxf(mx[1], u0.y * mk.y * r0);
        mx[2] = fmaxf(mx[2], u0.z * mk.z * r0);
        mx[3] = fmaxf(mx[3], u1.x * mk.x * r1);
        mx[4] = fmaxf(mx[4], u1.y * mk.y * r1);
        mx[5] = fmaxf(mx[5], u1.z * mk.z * r1);
    }
    #pragma unroll
    for (int k = 0; k < 6; k++) {
        #pragma unroll
        for (int o = 16; o > 0; o >>= 1)
            mx[k] = fmaxf(mx[k], __shfl_xor_sync(0xffffffffu, mx[k], o));
    }
    if (lane == 0) {
        float w1 = fminf(fmaxf(pw[1], 1e-10f), 1.f);
        float w2 = fminf(fmaxf(pw[2], 1e-10f), 1.f);
        float ast = g_ast[g]; ast = (ast == 0.f) ? 1e-8f : ast;
        float inva = 1.f / ast;
        float psum = 0.f;
        #pragma unroll
        for (int k = 0; k < 3; k++) {
            float uk = g_ukn[k][g] * inva;
            uk += w1 * (mx[k] + 1e-8f);          // l=0: power 1/1
            uk += w2 * sqrtf(mx[3 + k] + 1e-8f); // l=1: power 1/2
            uk *= (1.f / 3.f);                   // / MAXLEN
            psum += -logf(uk + 1e-8f);
        }
        atomicAdd(&g_scal[6], psum);
    }
}

// ---------------- final scalars ----------------
__global__ void k_final(float* __restrict__ out) {
    if (threadIdx.x == 0) {
        float info = (g_scal[0] + g_scal[1] + g_scal[2]) * (1.f / (3.f * (float)E_));
        float l2   = (g_scal[3] + g_scal[4] + g_scal[5]) * (1.f / (3.f * 2.f * (float)G_));
        float path = g_scal[6] * (1.f / (3.f * (float)G_));
        out[C_ * G_ * D_ + 0] = info;
        out[C_ * G_ * D_ + 1] = path;
        out[C_ * G_ * D_ + 2] = l2;
    }
}

extern "C" void kernel_launch(void* const* d_in, const int* in_sizes, int n_in,
                              void* d_out, int out_size) {
    const float* hg  = (const float*)d_in[0];
    const float* H   = (const float*)d_in[1];
    const float* pw  = (const float*)d_in[2];
    const float* sij = (const float*)d_in[3];
    const int*   ei  = (const int*)d_in[4];
    // d_in[5] = batch (derivable, unused)
    const int*   s   = (const int*)d_in[6];
    const int*   t   = (const int*)d_in[7];
    float* out = (float*)d_out;

    const int4*   src4 = (const int4*)ei;
    const int4*   dst4 = (const int4*)(ei + E_);
    const float4* sij4 = (const float4*)sij;

    k_init<<<1024, 256>>>(hg, H, out);
    k_edge1<<<1024, 256>>>(src4, dst4, sij4, s, t);
    k_edge2<<<1024, 256>>>(src4, dst4, sij);
    k_path<<<G_ / 8, 256>>>(pw);
    k_final<<<1, 32>>>(out);
}

// round 13
// speedup vs baseline: 1.0295x; 1.0295x over previous
#include <cuda_runtime.h>
#include <math.h>

#define G_ 256
#define M_ 256
#define N_ 65536
#define E_ 1048576
#define C_ 3
#define K_ 5
#define D_ 128
#define E1BLK 512           // edge-work blocks in k_edge1
#define ATTBLK 96           // attention blocks appended to k_edge1's grid
#define E2BLK 512           // blocks in k_edge2

// Scratch. CUDA zero-initializes __device__ globals at module load; every kernel
// call restores the all-zero state via k_clean (sparse, bitmask-driven), so the
// "zero at entry" invariant holds on every graph replay. Dirty-set tracking:
//   u0a dirty  ⊆ g_act cells   (written iff act bit set, same condition)
//   mka dirty  ⊆ g_actk cells
//   u1a dirty  ⊆ g_actk cells  (edge2 writes gated on actk[dst])
__device__ float4 g_u0a[N_];         // u0[c] , a0   (row s[g] of Mdj / Adj)
__device__ float4 g_mka[N_];         // mk[c] , ak   (col t[g])
__device__ float4 g_u1a[N_];         // u1[c] , a1   (one propagation step)
__device__ unsigned g_act[N_ / 32];  // bitmask: a0[idx] != 0 (row-active)
__device__ unsigned g_actk[N_ / 32]; // bitmask: ak[idx] != 0 (col-active)
__device__ float g_ukn[C_][G_];      // Mdj[g,s,t]
__device__ float g_ast[G_];          // Adj[g,s,t]
__device__ float g_scal[7];          // info[0..2], l2[3..5], path[6]

// One-instruction 16B atomic add (sm_90+: red.global.add.v4.f32).
__device__ __forceinline__ void red_add_v4(float4* p, float a, float b, float c, float d) {
    asm volatile("red.global.add.v4.f32 [%0], {%1, %2, %3, %4};"
                 :: "l"(p), "f"(a), "f"(b), "f"(c), "f"(d) : "memory");
}

// ---------------- edge pass 1 (blocks 0..E1BLK-1) + attention (blocks E1BLK..) ----
__global__ void __launch_bounds__(256) k_edge1(const int4* __restrict__ src4,
                                               const int4* __restrict__ dst4,
                                               const float4* __restrict__ sij4,
                                               const int* __restrict__ s,
                                               const int* __restrict__ t,
                                               const float* __restrict__ hg,
                                               const float* __restrict__ H,
                                               float* __restrict__ out) {
    int lane = threadIdx.x & 31;
    if (blockIdx.x >= E1BLK) {
        // Attention: one warp per (c,g) unit; 768 units on 96 blocks.
        int w = ((blockIdx.x - E1BLK) << 3) + (threadIdx.x >> 5);
        int c = w >> 8, g = w & 255;
        const float* Hc = H + c * K_ * D_;
        float h[4];
        #pragma unroll
        for (int j = 0; j < 4; j++) h[j] = hg[g * D_ + lane + 32 * j];
        float sc[K_];
        #pragma unroll
        for (int k = 0; k < K_; k++) {
            float x = 0.f;
            #pragma unroll
            for (int j = 0; j < 4; j++) x += h[j] * Hc[k * D_ + lane + 32 * j];
            #pragma unroll
            for (int o = 16; o > 0; o >>= 1) x += __shfl_xor_sync(0xffffffffu, x, o);
            sc[k] = x;
        }
        float mx = sc[0];
        #pragma unroll
        for (int k = 1; k < K_; k++) mx = fmaxf(mx, sc[k]);
        float ex[K_], se = 0.f;
        #pragma unroll
        for (int k = 0; k < K_; k++) { ex[k] = __expf(sc[k] - mx); se += ex[k]; }
        float inv = 1.f / se;
        #pragma unroll
        for (int j = 0; j < 4; j++) {
            float o = 0.f;
            #pragma unroll
            for (int k = 0; k < K_; k++) o += ex[k] * inv * Hc[k * D_ + lane + 32 * j];
            out[w * D_ + lane + 32 * j] = o;
        }
        return;
    }

    __shared__ int stp[G_];   // s | (t<<16)
    for (int j = threadIdx.x; j < G_; j += 256) stp[j] = s[j] | (t[j] << 16);
    __syncthreads();

    float acc[6] = {0.f, 0.f, 0.f, 0.f, 0.f, 0.f};
    const int NV = E_ / 4;
    const int gstr = E1BLK * 256;
    for (int i = blockIdx.x * 256 + threadIdx.x; i < NV; i += gstr) {
        int4 sv = src4[i];
        int4 dv = dst4[i];
        float4 v0 = sij4[i];
        float4 v1 = sij4[(E_ / 4) + i];
        float4 v2 = sij4[2 * (E_ / 4) + i];
        int svv[4] = {sv.x, sv.y, sv.z, sv.w};
        int dvv[4] = {dv.x, dv.y, dv.z, dv.w};
        float vv[4][3] = {{v0.x, v1.x, v2.x}, {v0.y, v1.y, v2.y},
                          {v0.z, v1.z, v2.z}, {v0.w, v1.w, v2.w}};
        #pragma unroll
        for (int q = 0; q < 4; q++) {
            int g = svv[q] >> 8, r = svv[q] & 255, c = dvv[q] & 255;
            #pragma unroll
            for (int k = 0; k < 3; k++) {
                float x = vv[q][k];
                acc[k]     += x * __logf(2.f * x + 1e-6f)
                            + (1.f - x) * __logf((1.f - x) * (1.f / 0.500001f) + 1e-6f);
                acc[3 + k] += x * x;
            }
            int stv = stp[g];
            bool hr = (r == (stv & 0xffff));
            bool hc = (c == (stv >> 16));
            if (hr) {
                int idx = dvv[q];  // == (g<<8)|c (dst is same-group by construction)
                red_add_v4(&g_u0a[idx], vv[q][0], vv[q][1], vv[q][2], 1.f);
                atomicOr(&g_act[idx >> 5], 1u << (idx & 31));
                if (hc) {
                    atomicAdd(&g_ukn[0][g], vv[q][0]);
                    atomicAdd(&g_ukn[1][g], vv[q][1]);
                    atomicAdd(&g_ukn[2][g], vv[q][2]);
                    atomicAdd(&g_ast[g], 1.f);
                }
            }
            if (hc) {
                int idx = svv[q];  // == (g<<8)|r
                red_add_v4(&g_mka[idx], vv[q][0], vv[q][1], vv[q][2], 1.f);
                atomicOr(&g_actk[idx >> 5], 1u << (idx & 31));
            }
        }
    }
    __shared__ float red[6][8];
    int w = threadIdx.x >> 5;
    #pragma unroll
    for (int k = 0; k < 6; k++) {
        float x = acc[k];
        #pragma unroll
        for (int o = 16; o > 0; o >>= 1) x += __shfl_down_sync(0xffffffffu, x, o);
        if (lane == 0) red[k][w] = x;
    }
    __syncthreads();
    if (threadIdx.x < 6) {
        float x = 0.f;
        #pragma unroll
        for (int j = 0; j < 8; j++) x += red[threadIdx.x][j];
        atomicAdd(&g_scal[threadIdx.x], x);
    }
}

// ---------------- edge pass 2: dual-bitmask-gated propagation ----------------
// Edge matters only if act[src] && actk[dst] (~0.4% of edges); this also
// guarantees u1a dirty cells ⊆ actk, which k_clean relies on.
__global__ void __launch_bounds__(256) k_edge2(const int4* __restrict__ src4,
                                               const int4* __restrict__ dst4,
                                               const float* __restrict__ sij) {
    __shared__ unsigned act_s[N_ / 32];    // 8 KB: row-active
    __shared__ unsigned actk_s[N_ / 32];   // 8 KB: col-active
    for (int j = threadIdx.x; j < N_ / 32; j += 256) {
        act_s[j] = g_act[j];
        actk_s[j] = g_actk[j];
    }
    __syncthreads();

    const int NV = E_ / 4;
    const int gstr = E2BLK * 256;
    for (int i = blockIdx.x * 256 + threadIdx.x; i < NV; i += gstr) {
        int4 sv = src4[i];
        int4 dv = dst4[i];
        int svv[4] = {sv.x, sv.y, sv.z, sv.w};
        int dvv[4] = {dv.x, dv.y, dv.z, dv.w};
        unsigned b[4];
        #pragma unroll
        for (int q = 0; q < 4; q++)
            b[q] = ((act_s[svv[q] >> 5] >> (svv[q] & 31))
                  & (actk_s[dvv[q] >> 5] >> (dvv[q] & 31))) & 1u;
        int ebase = 4 * i;
        #pragma unroll
        for (int q = 0; q < 4; q++) {
            if (b[q]) {
                float4 u = g_u0a[svv[q]];      // one 16B gather: u0[3], a0
                int e = ebase + q;
                red_add_v4(&g_u1a[dvv[q]],
                           u.x * sij[e], u.y * sij[E_ + e], u.z * sij[2 * E_ + e], u.w);
            }
        }
    }
}

// ---------------- path loss: sparse per-group max over mk-active cells ----------------
__global__ void __launch_bounds__(256) k_path(const float* __restrict__ pw) {
    int g = (blockIdx.x << 3) + (threadIdx.x >> 5);   // 32 blocks * 8 warps = 256 groups
    int lane = threadIdx.x & 31;
    unsigned wd = g_actk[(g << 3) + (lane >> 2)];
    unsigned byte = (wd >> ((lane & 3) << 3)) & 0xffu;
    float mx[6] = {0.f, 0.f, 0.f, 0.f, 0.f, 0.f};
    while (byte) {
        int j = __ffs(byte) - 1;
        byte &= byte - 1;
        int idx = (g << 8) + (lane << 3) + j;
        float4 u0 = g_u0a[idx];
        float4 mk = g_mka[idx];
        float4 u1 = g_u1a[idx];
        float d0 = u0.w * mk.w; d0 = (d0 == 0.f) ? 1e-8f : d0;
        float d1 = u1.w * mk.w; d1 = (d1 == 0.f) ? 1e-8f : d1;
        float r0 = 1.f / d0, r1 = 1.f / d1;
        mx[0] = fmaxf(mx[0], u0.x * mk.x * r0);
        mx[1] = fmaxf(mx[1], u0.y * mk.y * r0);
        mx[2] = fmaxf(mx[2], u0.z * mk.z * r0);
        mx[3] = fmaxf(mx[3], u1.x * mk.x * r1);
        mx[4] = fmaxf(mx[4], u1.y * mk.y * r1);
        mx[5] = fmaxf(mx[5], u1.z * mk.z * r1);
    }
    #pragma unroll
    for (int k = 0; k < 6; k++) {
        #pragma unroll
        for (int o = 16; o > 0; o >>= 1)
            mx[k] = fmaxf(mx[k], __shfl_xor_sync(0xffffffffu, mx[k], o));
    }
    if (lane == 0) {
        float w1 = fminf(fmaxf(pw[1], 1e-10f), 1.f);
        float w2 = fminf(fmaxf(pw[2], 1e-10f), 1.f);
        float ast = g_ast[g]; ast = (ast == 0.f) ? 1e-8f : ast;
        float inva = 1.f / ast;
        float psum = 0.f;
        #pragma unroll
        for (int k = 0; k < 3; k++) {
            float uk = g_ukn[k][g] * inva;
            uk += w1 * (mx[k] + 1e-8f);          // l=0: power 1/1
            uk += w2 * sqrtf(mx[3 + k] + 1e-8f); // l=1: power 1/2
            uk *= (1.f / 3.f);                   // / MAXLEN
            psum += -logf(uk + 1e-8f);
        }
        atomicAdd(&g_scal[6], psum);
    }
}

// ---------------- final scalars + sparse scratch cleanup ----------------
// Restores the all-zero invariant for the next kernel_launch / graph replay.
__global__ void __launch_bounds__(256) k_clean(float* __restrict__ out) {
    int gtid = blockIdx.x * 256 + threadIdx.x;   // 64 blocks * 256 = 16384
    float4 z4 = make_float4(0.f, 0.f, 0.f, 0.f);
    if (gtid == 0) {
        float info = (g_scal[0] + g_scal[1] + g_scal[2]) * (1.f / (3.f * (float)E_));
        float l2   = (g_scal[3] + g_scal[4] + g_scal[5]) * (1.f / (3.f * 2.f * (float)G_));
        float path = g_scal[6] * (1.f / (3.f * (float)G_));
        out[C_ * G_ * D_ + 0] = info;
        out[C_ * G_ * D_ + 1] = path;
        out[C_ * G_ * D_ + 2] = l2;
        #pragma unroll
        for (int k = 0; k < 7; k++) g_scal[k] = 0.f;
    }
    if (gtid < N_ / 32) {                          // 2048 act words
        unsigned w = g_act[gtid];
        while (w) {
            int j = __ffs(w) - 1;
            w &= w - 1;
            g_u0a[(gtid << 5) + j] = z4;
        }
        g_act[gtid] = 0u;
    } else if (gtid < 2 * (N_ / 32)) {             // 2048 actk words
        int q = gtid - N_ / 32;
        unsigned w = g_actk[q];
        while (w) {
            int j = __ffs(w) - 1;
            w &= w - 1;
            int idx = (q << 5) + j;
            g_mka[idx] = z4;
            g_u1a[idx] = z4;
        }
        g_actk[q] = 0u;
    } else if (gtid < 2 * (N_ / 32) + C_ * G_) {   // 768 ukn
        (&g_ukn[0][0])[gtid - 2 * (N_ / 32)] = 0.f;
    } else if (gtid < 2 * (N_ / 32) + C_ * G_ + G_) {  // 256 ast
        g_ast[gtid - 2 * (N_ / 32) - C_ * G_] = 0.f;
    }
}

extern "C" void kernel_launch(void* const* d_in, const int* in_sizes, int n_in,
                              void* d_out, int out_size) {
    const float* hg  = (const float*)d_in[0];
    const float* H   = (const float*)d_in[1];
    const float* pw  = (const float*)d_in[2];
    const float* sij = (const float*)d_in[3];
    const int*   ei  = (const int*)d_in[4];
    // d_in[5] = batch (derivable, unused)
    const int*   s   = (const int*)d_in[6];
    const int*   t   = (const int*)d_in[7];
    float* out = (float*)d_out;

    const int4*   src4 = (const int4*)ei;
    const int4*   dst4 = (const int4*)(ei + E_);
    const float4* sij4 = (const float4*)sij;

    k_edge1<<<E1BLK + ATTBLK, 256>>>(src4, dst4, sij4, s, t, hg, H, out);
    k_edge2<<<E2BLK, 256>>>(src4, dst4, sij);
    k_path<<<G_ / 8, 256>>>(pw);
    k_clean<<<64, 256>>>(out);
}

// round 15
// speedup vs baseline: 1.0309x; 1.0014x over previous
#include <cuda_runtime.h>
#include <math.h>

#define G_ 256
#define M_ 256
#define N_ 65536
#define E_ 1048576
#define C_ 3
#define K_ 5
#define D_ 128
#define OUT_SCAL (C_ * G_ * D_)   // index of the 3 scalar outputs

// Interleaved scratch: .x/.y/.z = per-class values, .w = adjacency count.
__device__ float4 g_u0a[N_];         // u0[c] , a0   (row s[g] of Mdj / Adj)
__device__ float4 g_mka[N_];         // mk[c] , ak   (col t[g])
__device__ float4 g_u1a[N_];         // u1[c] , a1   (one propagation step)
__device__ unsigned g_act[N_ / 32];  // bitmask: a0[idx] != 0 (row-active)
__device__ unsigned g_actk[N_ / 32]; // bitmask: ak[idx] != 0 (col-active)
__device__ float g_ukn[C_][G_];      // Mdj[g,s,t]
__device__ float g_ast[G_];          // Adj[g,s,t]
__device__ float g_scal[6];          // info[0..2], l2[3..5]

// One-instruction 16B atomic add (sm_90+: red.global.add.v4.f32).
__device__ __forceinline__ void red_add_v4(float4* p, float a, float b, float c, float d) {
    asm volatile("red.global.add.v4.f32 [%0], {%1, %2, %3, %4};"
                 :: "l"(p), "f"(a), "f"(b), "f"(c), "f"(d) : "memory");
}

// ---------------- init: zero scratch + attention embedding ----------------
__global__ void __launch_bounds__(256) k_init(const float* __restrict__ hg,
                                              const float* __restrict__ H,
                                              float* __restrict__ out) {
    int gtid = blockIdx.x * 256 + threadIdx.x;
    int gstr = gridDim.x * 256;
    float4 z4 = make_float4(0.f, 0.f, 0.f, 0.f);
    for (int j = gtid; j < N_; j += gstr) {
        g_u0a[j] = z4; g_mka[j] = z4; g_u1a[j] = z4;
    }
    for (int j = gtid; j < N_ / 32; j += gstr) { g_act[j] = 0u; g_actk[j] = 0u; }
    if (gtid < C_ * G_) (&g_ukn[0][0])[gtid] = 0.f;
    if (gtid < G_) g_ast[gtid] = 0.f;
    if (gtid < 6) g_scal[gtid] = 0.f;
    if (gtid == 6) out[OUT_SCAL + 1] = 0.f;   // path accumulator slot

    // Attention: one warp per (c,g) unit; 768 units on blocks 0..95.
    int lane = threadIdx.x & 31;
    int w = (blockIdx.x << 3) + (threadIdx.x >> 5);
    if (w < C_ * G_) {
        int c = w >> 8, g = w & 255;
        const float* Hc = H + c * K_ * D_;
        float h[4];
        #pragma unroll
        for (int j = 0; j < 4; j++) h[j] = hg[g * D_ + lane + 32 * j];
        float sc[K_];
        #pragma unroll
        for (int k = 0; k < K_; k++) {
            float x = 0.f;
            #pragma unroll
            for (int j = 0; j < 4; j++) x += h[j] * Hc[k * D_ + lane + 32 * j];
            #pragma unroll
            for (int o = 16; o > 0; o >>= 1) x += __shfl_xor_sync(0xffffffffu, x, o);
            sc[k] = x;
        }
        float mx = sc[0];
        #pragma unroll
        for (int k = 1; k < K_; k++) mx = fmaxf(mx, sc[k]);
        float ex[K_], se = 0.f;
        #pragma unroll
        for (int k = 0; k < K_; k++) { ex[k] = __expf(sc[k] - mx); se += ex[k]; }
        float inv = 1.f / se;
        #pragma unroll
        for (int j = 0; j < 4; j++) {
            float o = 0.f;
            #pragma unroll
            for (int k = 0; k < K_; k++) o += ex[k] * inv * Hc[k * D_ + lane + 32 * j];
            out[w * D_ + lane + 32 * j] = o;
        }
    }
}

// ---------------- edge pass 1: info/l2 + gated row/col scatters ----------------
__global__ void __launch_bounds__(256) k_edge1(const int4* __restrict__ src4,
                                               const int4* __restrict__ dst4,
                                               const float4* __restrict__ sij4,
                                               const int* __restrict__ s,
                                               const int* __restrict__ t) {
    __shared__ int stp[G_];   // s | (t<<16)
    for (int j = threadIdx.x; j < G_; j += 256) stp[j] = s[j] | (t[j] << 16);
    __syncthreads();

    float acc[6] = {0.f, 0.f, 0.f, 0.f, 0.f, 0.f};
    const int NV = E_ / 4;
    int gstr = gridDim.x * 256;
    for (int i = blockIdx.x * 256 + threadIdx.x; i < NV; i += gstr) {
        int4 sv = src4[i];
        int4 dv = dst4[i];
        float4 v0 = sij4[i];
        float4 v1 = sij4[(E_ / 4) + i];
        float4 v2 = sij4[2 * (E_ / 4) + i];
        int svv[4] = {sv.x, sv.y, sv.z, sv.w};
        int dvv[4] = {dv.x, dv.y, dv.z, dv.w};
        float vv[4][3] = {{v0.x, v1.x, v2.x}, {v0.y, v1.y, v2.y},
                          {v0.z, v1.z, v2.z}, {v0.w, v1.w, v2.w}};
        #pragma unroll
        for (int q = 0; q < 4; q++) {
            int g = svv[q] >> 8, r = svv[q] & 255, c = dvv[q] & 255;
            #pragma unroll
            for (int k = 0; k < 3; k++) {
                float x = vv[q][k];
                acc[k]     += x * __logf(2.f * x + 1e-6f)
                            + (1.f - x) * __logf((1.f - x) * (1.f / 0.500001f) + 1e-6f);
                acc[3 + k] += x * x;
            }
            int stv = stp[g];
            bool hr = (r == (stv & 0xffff));
            bool hc = (c == (stv >> 16));
            if (hr) {
                int idx = dvv[q];  // == (g<<8)|c (dst is same-group by construction)
                red_add_v4(&g_u0a[idx], vv[q][0], vv[q][1], vv[q][2], 1.f);
                atomicOr(&g_act[idx >> 5], 1u << (idx & 31));
                if (hc) {
                    atomicAdd(&g_ukn[0][g], vv[q][0]);
                    atomicAdd(&g_ukn[1][g], vv[q][1]);
                    atomicAdd(&g_ukn[2][g], vv[q][2]);
                    atomicAdd(&g_ast[g], 1.f);
                }
            }
            if (hc) {
                int idx = svv[q];  // == (g<<8)|r
                red_add_v4(&g_mka[idx], vv[q][0], vv[q][1], vv[q][2], 1.f);
                atomicOr(&g_actk[idx >> 5], 1u << (idx & 31));
            }
        }
    }
    __shared__ float red[6][8];
    int lane = threadIdx.x & 31, w = threadIdx.x >> 5;
    #pragma unroll
    for (int k = 0; k < 6; k++) {
        float x = acc[k];
        #pragma unroll
        for (int o = 16; o > 0; o >>= 1) x += __shfl_down_sync(0xffffffffu, x, o);
        if (lane == 0) red[k][w] = x;
    }
    __syncthreads();
    if (threadIdx.x < 6) {
        float x = 0.f;
        #pragma unroll
        for (int j = 0; j < 8; j++) x += red[threadIdx.x][j];
        atomicAdd(&g_scal[threadIdx.x], x);
    }
}

// ---------------- edge pass 2: bitmask-gated one-step propagation ----------------
__global__ void __launch_bounds__(256) k_edge2(const int4* __restrict__ src4,
                                               const int4* __restrict__ dst4,
                                               const float* __restrict__ sij) {
    __shared__ unsigned act_s[N_ / 32];   // 8 KB
    for (int j = threadIdx.x; j < N_ / 32; j += 256) act_s[j] = g_act[j];
    __syncthreads();

    const int NV = E_ / 4;
    int gstr = gridDim.x * 256;
    for (int i = blockIdx.x * 256 + threadIdx.x; i < NV; i += gstr) {
        int4 sv = src4[i];
        int4 dv = dst4[i];
        int svv[4] = {sv.x, sv.y, sv.z, sv.w};
        int dvv[4] = {dv.x, dv.y, dv.z, dv.w};
        unsigned b[4];
        #pragma unroll
        for (int q = 0; q < 4; q++)
            b[q] = (act_s[svv[q] >> 5] >> (svv[q] & 31)) & 1u;
        int ebase = 4 * i;
        #pragma unroll
        for (int q = 0; q < 4; q++) {
            if (b[q]) {
                float4 u = g_u0a[svv[q]];      // one 16B gather: u0[3], a0
                int e = ebase + q;
                red_add_v4(&g_u1a[dvv[q]],
                           u.x * sij[e], u.y * sij[E_ + e], u.z * sij[2 * E_ + e], u.w);
            }
        }
    }
}

// ---------------- path loss: sparse per-group max + fused scalar outputs ----------------
// loc values vanish wherever mk==0, so only g_actk cells (~16/group) matter.
// One warp per group. Per-group tail is atomically accumulated straight into
// out[OUT_SCAL+1] (zeroed by k_init this same launch sequence — stream-ordered,
// no cross-launch state). Block 0 thread 0 writes info/l2 (g_scal complete
// since k_edge1 finished, stream-ordered).
__global__ void __launch_bounds__(256) k_path(const float* __restrict__ pw,
                                              float* __restrict__ out) {
    int g = (blockIdx.x << 3) + (threadIdx.x >> 5);   // 32 blocks * 8 warps = 256 groups
    int lane = threadIdx.x & 31;
    unsigned wd = g_actk[(g << 3) + (lane >> 2)];
    unsigned byte = (wd >> ((lane & 3) << 3)) & 0xffu;
    float mx[6] = {0.f, 0.f, 0.f, 0.f, 0.f, 0.f};
    while (byte) {
        int j = __ffs(byte) - 1;
        byte &= byte - 1;
        int idx = (g << 8) + (lane << 3) + j;
        float4 u0 = g_u0a[idx];
        float4 mk = g_mka[idx];
        float4 u1 = g_u1a[idx];
        float d0 = u0.w * mk.w; d0 = (d0 == 0.f) ? 1e-8f : d0;
        float d1 = u1.w * mk.w; d1 = (d1 == 0.f) ? 1e-8f : d1;
        float r0 = 1.f / d0, r1 = 1.f / d1;
        mx[0] = fmaxf(mx[0], u0.x * mk.x * r0);
        mx[1] = fmaxf(mx[1], u0.y * mk.y * r0);
        mx[2] = fmaxf(mx[2], u0.z * mk.z * r0);
        mx[3] = fmaxf(mx[3], u1.x * mk.x * r1);
        mx[4] = fmaxf(mx[4], u1.y * mk.y * r1);
        mx[5] = fmaxf(mx[5], u1.z * mk.z * r1);
    }
    #pragma unroll
    for (int k = 0; k < 6; k++) {
        #pragma unroll
        for (int o = 16; o > 0; o >>= 1)
            mx[k] = fmaxf(mx[k], __shfl_xor_sync(0xffffffffu, mx[k], o));
    }
    if (lane == 0) {
        float w1 = fminf(fmaxf(pw[1], 1e-10f), 1.f);
        float w2 = fminf(fmaxf(pw[2], 1e-10f), 1.f);
        float ast = g_ast[g]; ast = (ast == 0.f) ? 1e-8f : ast;
        float inva = 1.f / ast;
        float psum = 0.f;
        #pragma unroll
        for (int k = 0; k < 3; k++) {
            float uk = g_ukn[k][g] * inva;
            uk += w1 * (mx[k] + 1e-8f);          // l=0: power 1/1
            uk += w2 * sqrtf(mx[3 + k] + 1e-8f); // l=1: power 1/2
            uk *= (1.f / 3.f);                   // / MAXLEN
            psum += -logf(uk + 1e-8f);
        }
        atomicAdd(&out[OUT_SCAL + 1], psum * (1.f / (3.f * (float)G_)));
    }
    if (blockIdx.x == 0 && threadIdx.x == 0) {
        out[OUT_SCAL + 0] = (g_scal[0] + g_scal[1] + g_scal[2]) * (1.f / (3.f * (float)E_));
        out[OUT_SCAL + 2] = (g_scal[3] + g_scal[4] + g_scal[5]) * (1.f / (3.f * 2.f * (float)G_));
    }
}

extern "C" void kernel_launch(void* const* d_in, const int* in_sizes, int n_in,
                              void* d_out, int out_size) {
    const float* hg  = (const float*)d_in[0];
    const float* H   = (const float*)d_in[1];
    const float* pw  = (const float*)d_in[2];
    const float* sij = (const float*)d_in[3];
    const int*   ei  = (const int*)d_in[4];
    // d_in[5] = batch (derivable, unused)
    const int*   s   = (const int*)d_in[6];
    const int*   t   = (const int*)d_in[7];
    float* out = (float*)d_out;

    const int4*   src4 = (const int4*)ei;
    const int4*   dst4 = (const int4*)(ei + E_);
    const float4* sij4 = (const float4*)sij;

    k_init<<<1024, 256>>>(hg, H, out);
    k_edge1<<<1024, 256>>>(src4, dst4, sij4, s, t);
    k_edge2<<<512, 256>>>(src4, dst4, sij);
    k_path<<<G_ / 8, 256>>>(pw, out);
}

// round 16
// speedup vs baseline: 1.0426x; 1.0114x over previous
#include <cuda_runtime.h>
#include <math.h>

#define G_ 256
#define M_ 256
#define N_ 65536
#define E_ 1048576
#define C_ 3
#define K_ 5
#define D_ 128
#define OUT_SCAL (C_ * G_ * D_)   // index of the 3 scalar outputs

// Interleaved scratch: .x/.y/.z = per-class values, .w = adjacency count.
__device__ float4 g_u0a[N_];         // u0[c] , a0   (row s[g] of Mdj / Adj)
__device__ float4 g_mka[N_];         // mk[c] , ak   (col t[g])
__device__ float4 g_u1a[N_];         // u1[c] , a1   (one propagation step)
__device__ unsigned g_act[N_ / 32];  // bitmask: a0[idx] != 0 (row-active)
__device__ unsigned g_actk[N_ / 32]; // bitmask: ak[idx] != 0 (col-active)
__device__ float g_ukn[C_][G_];      // Mdj[g,s,t]
__device__ float g_ast[G_];          // Adj[g,s,t]
__device__ float g_scal[6];          // info[0..2], l2[3..5]

// One-instruction 16B atomic add (sm_90+: red.global.add.v4.f32).
__device__ __forceinline__ void red_add_v4(float4* p, float a, float b, float c, float d) {
    asm volatile("red.global.add.v4.f32 [%0], {%1, %2, %3, %4};"
                 :: "l"(p), "f"(a), "f"(b), "f"(c), "f"(d) : "memory");
}

// ---------------- init: zero scratch + attention embedding ----------------
__global__ void __launch_bounds__(256) k_init(const float* __restrict__ hg,
                                              const float* __restrict__ H,
                                              float* __restrict__ out) {
    int gtid = blockIdx.x * 256 + threadIdx.x;
    int gstr = gridDim.x * 256;
    float4 z4 = make_float4(0.f, 0.f, 0.f, 0.f);
    for (int j = gtid; j < N_; j += gstr) {
        g_u0a[j] = z4; g_mka[j] = z4; g_u1a[j] = z4;
    }
    for (int j = gtid; j < N_ / 32; j += gstr) { g_act[j] = 0u; g_actk[j] = 0u; }
    if (gtid < C_ * G_) (&g_ukn[0][0])[gtid] = 0.f;
    if (gtid < G_) g_ast[gtid] = 0.f;
    if (gtid < 6) g_scal[gtid] = 0.f;
    if (gtid == 6) out[OUT_SCAL + 1] = 0.f;   // path accumulator slot

    // Attention: one warp per (c,g) unit; 768 units on blocks 0..95.
    int lane = threadIdx.x & 31;
    int w = (blockIdx.x << 3) + (threadIdx.x >> 5);
    if (w < C_ * G_) {
        int c = w >> 8, g = w & 255;
        const float* Hc = H + c * K_ * D_;
        float h[4];
        #pragma unroll
        for (int j = 0; j < 4; j++) h[j] = hg[g * D_ + lane + 32 * j];
        float sc[K_];
        #pragma unroll
        for (int k = 0; k < K_; k++) {
            float x = 0.f;
            #pragma unroll
            for (int j = 0; j < 4; j++) x += h[j] * Hc[k * D_ + lane + 32 * j];
            #pragma unroll
            for (int o = 16; o > 0; o >>= 1) x += __shfl_xor_sync(0xffffffffu, x, o);
            sc[k] = x;
        }
        float mx = sc[0];
        #pragma unroll
        for (int k = 1; k < K_; k++) mx = fmaxf(mx, sc[k]);
        float ex[K_], se = 0.f;
        #pragma unroll
        for (int k = 0; k < K_; k++) { ex[k] = __expf(sc[k] - mx); se += ex[k]; }
        float inv = 1.f / se;
        #pragma unroll
        for (int j = 0; j < 4; j++) {
            float o = 0.f;
            #pragma unroll
            for (int k = 0; k < K_; k++) o += ex[k] * inv * Hc[k * D_ + lane + 32 * j];
            out[w * D_ + lane + 32 * j] = o;
        }
    }
}

// ---------------- edge pass 1: info/l2 + gated row/col scatters ----------------
__global__ void __launch_bounds__(256) k_edge1(const int4* __restrict__ src4,
                                               const int4* __restrict__ dst4,
                                               const float4* __restrict__ sij4,
                                               const int* __restrict__ s,
                                               const int* __restrict__ t) {
    __shared__ int stp[G_];   // s | (t<<16)
    for (int j = threadIdx.x; j < G_; j += 256) stp[j] = s[j] | (t[j] << 16);
    __syncthreads();

    float acc[6] = {0.f, 0.f, 0.f, 0.f, 0.f, 0.f};
    const int NV = E_ / 4;
    int gstr = gridDim.x * 256;
    for (int i = blockIdx.x * 256 + threadIdx.x; i < NV; i += gstr) {
        int4 sv = src4[i];
        int4 dv = dst4[i];
        float4 v0 = sij4[i];
        float4 v1 = sij4[(E_ / 4) + i];
        float4 v2 = sij4[2 * (E_ / 4) + i];
        int svv[4] = {sv.x, sv.y, sv.z, sv.w};
        int dvv[4] = {dv.x, dv.y, dv.z, dv.w};
        float vv[4][3] = {{v0.x, v1.x, v2.x}, {v0.y, v1.y, v2.y},
                          {v0.z, v1.z, v2.z}, {v0.w, v1.w, v2.w}};
        #pragma unroll
        for (int q = 0; q < 4; q++) {
            int g = svv[q] >> 8, r = svv[q] & 255, c = dvv[q] & 255;
            #pragma unroll
            for (int k = 0; k < 3; k++) {
                float x = vv[q][k];
                acc[k]     += x * __logf(2.f * x + 1e-6f)
                            + (1.f - x) * __logf((1.f - x) * (1.f / 0.500001f) + 1e-6f);
                acc[3 + k] += x * x;
            }
            int stv = stp[g];
            bool hr = (r == (stv & 0xffff));
            bool hc = (c == (stv >> 16));
            if (hr) {
                int idx = dvv[q];  // == (g<<8)|c (dst is same-group by construction)
                red_add_v4(&g_u0a[idx], vv[q][0], vv[q][1], vv[q][2], 1.f);
                atomicOr(&g_act[idx >> 5], 1u << (idx & 31));
                if (hc) {
                    atomicAdd(&g_ukn[0][g], vv[q][0]);
                    atomicAdd(&g_ukn[1][g], vv[q][1]);
                    atomicAdd(&g_ukn[2][g], vv[q][2]);
                    atomicAdd(&g_ast[g], 1.f);
                }
            }
            if (hc) {
                int idx = svv[q];  // == (g<<8)|r
                red_add_v4(&g_mka[idx], vv[q][0], vv[q][1], vv[q][2], 1.f);
                atomicOr(&g_actk[idx >> 5], 1u << (idx & 31));
            }
        }
    }
    __shared__ float red[6][8];
    int lane = threadIdx.x & 31, w = threadIdx.x >> 5;
    #pragma unroll
    for (int k = 0; k < 6; k++) {
        float x = acc[k];
        #pragma unroll
        for (int o = 16; o > 0; o >>= 1) x += __shfl_down_sync(0xffffffffu, x, o);
        if (lane == 0) red[k][w] = x;
    }
    __syncthreads();
    if (threadIdx.x < 6) {
        float x = 0.f;
        #pragma unroll
        for (int j = 0; j < 8; j++) x += red[threadIdx.x][j];
        atomicAdd(&g_scal[threadIdx.x], x);
    }
}

// ---------------- edge pass 2: bitmask-gated one-step propagation ----------------
__global__ void __launch_bounds__(256) k_edge2(const int4* __restrict__ src4,
                                               const int4* __restrict__ dst4,
                                               const float* __restrict__ sij) {
    __shared__ unsigned act_s[N_ / 32];   // 8 KB
    for (int j = threadIdx.x; j < N_ / 32; j += 256) act_s[j] = g_act[j];
    __syncthreads();

    const int NV = E_ / 4;
    int gstr = gridDim.x * 256;
    for (int i = blockIdx.x * 256 + threadIdx.x; i < NV; i += gstr) {
        int4 sv = src4[i];
        int4 dv = dst4[i];
        int svv[4] = {sv.x, sv.y, sv.z, sv.w};
        int dvv[4] = {dv.x, dv.y, dv.z, dv.w};
        unsigned b[4];
        #pragma unroll
        for (int q = 0; q < 4; q++)
            b[q] = (act_s[svv[q] >> 5] >> (svv[q] & 31)) & 1u;
        int ebase = 4 * i;
        #pragma unroll
        for (int q = 0; q < 4; q++) {
            if (b[q]) {
                float4 u = g_u0a[svv[q]];      // one 16B gather: u0[3], a0
                int e = ebase + q;
                red_add_v4(&g_u1a[dvv[q]],
                           u.x * sij[e], u.y * sij[E_ + e], u.z * sij[2 * E_ + e], u.w);
            }
        }
    }
}

// ---------------- path loss: sparse per-group max + fused scalar outputs ----------------
// loc values vanish wherever mk==0, so only g_actk cells (~16/group) matter.
// One warp per group. Per-group tail is atomically accumulated straight into
// out[OUT_SCAL+1] (zeroed by k_init this same launch sequence — stream-ordered,
// no cross-launch state). Block 0 thread 0 writes info/l2 (g_scal complete
// since k_edge1 finished, stream-ordered).
__global__ void __launch_bounds__(256) k_path(const float* __restrict__ pw,
                                              float* __restrict__ out) {
    int g = (blockIdx.x << 3) + (threadIdx.x >> 5);   // 32 blocks * 8 warps = 256 groups
    int lane = threadIdx.x & 31;
    unsigned wd = g_actk[(g << 3) + (lane >> 2)];
    unsigned byte = (wd >> ((lane & 3) << 3)) & 0xffu;
    float mx[6] = {0.f, 0.f, 0.f, 0.f, 0.f, 0.f};
    while (byte) {
        int j = __ffs(byte) - 1;
        byte &= byte - 1;
        int idx = (g << 8) + (lane << 3) + j;
        float4 u0 = g_u0a[idx];
        float4 mk = g_mka[idx];
        float4 u1 = g_u1a[idx];
        float d0 = u0.w * mk.w; d0 = (d0 == 0.f) ? 1e-8f : d0;
        float d1 = u1.w * mk.w; d1 = (d1 == 0.f) ? 1e-8f : d1;
        float r0 = 1.f / d0, r1 = 1.f / d1;
        mx[0] = fmaxf(mx[0], u0.x * mk.x * r0);
        mx[1] = fmaxf(mx[1], u0.y * mk.y * r0);
        mx[2] = fmaxf(mx[2], u0.z * mk.z * r0);
        mx[3] = fmaxf(mx[3], u1.x * mk.x * r1);
        mx[4] = fmaxf(mx[4], u1.y * mk.y * r1);
        mx[5] = fmaxf(mx[5], u1.z * mk.z * r1);
    }
    #pragma unroll
    for (int k = 0; k < 6; k++) {
        #pragma unroll
        for (int o = 16; o > 0; o >>= 1)
            mx[k] = fmaxf(mx[k], __shfl_xor_sync(0xffffffffu, mx[k], o));
    }
    if (lane == 0) {
        float w1 = fminf(fmaxf(pw[1], 1e-10f), 1.f);
        float w2 = fminf(fmaxf(pw[2], 1e-10f), 1.f);
        float ast = g_ast[g]; ast = (ast == 0.f) ? 1e-8f : ast;
        float inva = 1.f / ast;
        float psum = 0.f;
        #pragma unroll
        for (int k = 0; k < 3; k++) {
            float uk = g_ukn[k][g] * inva;
            uk += w1 * (mx[k] + 1e-8f);          // l=0: power 1/1
            uk += w2 * sqrtf(mx[3 + k] + 1e-8f); // l=1: power 1/2
            uk *= (1.f / 3.f);                   // / MAXLEN
            psum += -logf(uk + 1e-8f);
        }
        atomicAdd(&out[OUT_SCAL + 1], psum * (1.f / (3.f * (float)G_)));
    }
    if (blockIdx.x == 0 && threadIdx.x == 0) {
        out[OUT_SCAL + 0] = (g_scal[0] + g_scal[1] + g_scal[2]) * (1.f / (3.f * (float)E_));
        out[OUT_SCAL + 2] = (g_scal[3] + g_scal[4] + g_scal[5]) * (1.f / (3.f * 2.f * (float)G_));
    }
}

extern "C" void kernel_launch(void* const* d_in, const int* in_sizes, int n_in,
                              void* d_out, int out_size) {
    const float* hg  = (const float*)d_in[0];
    const float* H   = (const float*)d_in[1];
    const float* pw  = (const float*)d_in[2];
    const float* sij = (const float*)d_in[3];
    const int*   ei  = (const int*)d_in[4];
    // d_in[5] = batch (derivable, unused)
    const int*   s   = (const int*)d_in[6];
    const int*   t   = (const int*)d_in[7];
    float* out = (float*)d_out;

    const int4*   src4 = (const int4*)ei;
    const int4*   dst4 = (const int4*)(ei + E_);
    const float4* sij4 = (const float4*)sij;

    k_init<<<1024, 256>>>(hg, H, out);
    k_edge1<<<1024, 256>>>(src4, dst4, sij4, s, t);
    k_edge2<<<512, 256>>>(src4, dst4, sij);
    k_path<<<G_ / 8, 256>>>(pw, out);
}